// round 16
// baseline (speedup 1.0000x reference)
#include <cuda_runtime.h>
#include <cuda_fp16.h>
#include <cstdint>

#define S_   2048
#define D_   1024
#define H_   16
#define HD_  64
#define DFF_ 4096

__device__ __align__(16) __half g_sx [(long)H_ * S_ * S_];   // fp16 compact scores
__device__ __align__(16) float2 g_tau[H_ * S_];              // per-row {tau_q, scale}
__device__ __align__(16) __half g_x  [S_ * D_];
__device__ __align__(16) __half g_q  [S_ * D_];
__device__ __align__(16) __half g_k  [S_ * D_];
__device__ __align__(16) __half g_vt [S_ * D_];              // [h][64][slot] compacted
__device__ __align__(16) __half g_at [S_ * D_];
__device__ __align__(16) float  g_y  [S_ * D_];
__device__ __align__(16) __half g_h1 [S_ * DFF_];
__device__ __align__(16) __half g_wqkv[3 * D_ * D_];
__device__ __align__(16) __half g_wo[D_ * D_];
__device__ __align__(16) __half g_w1[DFF_ * D_], g_w2[D_ * DFF_];
__device__ int g_idx [S_];     // compact slot -> token
__device__ int g_rank[S_];     // token -> compact slot, -1 if masked
__device__ int g_meta[2];      // {cnt, cnt_pad}

#define MASKED_X (-30000.0f)

__device__ __forceinline__ uint32_t smem_u32(const void* p) {
    uint32_t a;
    asm("{ .reg .u64 t; cvta.to.shared.u64 t, %1; cvt.u32.u64 %0, t; }"
        : "=r"(a) : "l"(p));
    return a;
}

#define CP16(dst, src) \
    asm volatile("cp.async.cg.shared.global [%0], [%1], 16;" \
                 :: "r"(dst), "l"(src))

#define LDSM4(r, addr) \
    asm volatile("ldmatrix.sync.aligned.m8n8.x4.shared.b16 {%0,%1,%2,%3}, [%4];" \
                 : "=r"((r)[0]), "=r"((r)[1]), "=r"((r)[2]), "=r"((r)[3]) \
                 : "r"(addr))

#define MMA16816(d, a, b) \
    asm volatile("mma.sync.aligned.m16n8k16.row.col.f32.f16.f16.f32 " \
                 "{%0,%1,%2,%3}, {%4,%5,%6,%7}, {%8,%9}, {%0,%1,%2,%3};" \
                 : "+f"((d)[0]), "+f"((d)[1]), "+f"((d)[2]), "+f"((d)[3]) \
                 : "r"((a)[0]), "r"((a)[1]), "r"((a)[2]), "r"((a)[3]), \
                   "r"((b)[0]), "r"((b)[1]))

__device__ __forceinline__ uint32_t pack2(__half a, __half b) {
    __half2 h; h.x = a; h.y = b;
    return *(uint32_t*)&h;
}

// fp16 scores -> scaled probs, all-half2: p = s * relu(x - tau_q)^2
__device__ __forceinline__ uint32_t prob_tf(uint32_t u, uint32_t tq2, uint32_t s2) {
    const __half2 z = __float2half2_rn(0.f);
    __half2 t = __hmax2(__hsub2(*(__half2*)&u, *(__half2*)&tq2), z);
    t = __hmul2(__hmul2(t, t), *(__half2*)&s2);
    return *(const uint32_t*)&t;
}

// warp-per-row LayerNorm body (8 rows per 256-thread CTA)
__device__ __forceinline__ void ln_rows8(const float* __restrict__ X,
                                         const float* __restrict__ ga,
                                         const float* __restrict__ gb,
                                         __half* __restrict__ OH, long rowbase)
{
    const int w = threadIdx.x >> 5, lane = threadIdx.x & 31;
    const long row = rowbase + w;
    const float4* x4 = (const float4*)(X + row * D_);

    float4 v[8];
    float s = 0.f, sq = 0.f;
    #pragma unroll
    for (int i = 0; i < 8; i++) {
        v[i] = x4[i * 32 + lane];
        s  += v[i].x + v[i].y + v[i].z + v[i].w;
        sq += v[i].x*v[i].x + v[i].y*v[i].y + v[i].z*v[i].z + v[i].w*v[i].w;
    }
    #pragma unroll
    for (int o = 16; o > 0; o >>= 1) {
        s  += __shfl_xor_sync(0xffffffffu, s,  o);
        sq += __shfl_xor_sync(0xffffffffu, sq, o);
    }
    const float mu  = s * (1.0f / D_);
    const float var = fmaxf((sq - mu * mu * (float)D_) * (1.0f / (D_ - 1)), 0.0f);
    const float inv = 1.0f / (sqrtf(var) + 1e-6f);

    const float4* a4 = (const float4*)ga;
    const float4* b4 = (const float4*)gb;
    uint2* dst = (uint2*)(OH + row * D_);
    #pragma unroll
    for (int i = 0; i < 8; i++) {
        const float4 a = a4[i * 32 + lane];
        const float4 b = b4[i * 32 + lane];
        const float o0 = (v[i].x - mu) * inv * a.x + b.x;
        const float o1 = (v[i].y - mu) * inv * a.y + b.y;
        const float o2 = (v[i].z - mu) * inv * a.z + b.z;
        const float o3 = (v[i].w - mu) * inv * a.w + b.w;
        dst[i * 32 + lane] = make_uint2(pack2(__float2half_rn(o0), __float2half_rn(o1)),
                                        pack2(__float2half_rn(o2), __float2half_rn(o3)));
    }
}

// ---------------------------------------------------------------------------
// cvt_w: blocks [0,12288) weights->fp16; block 12288 mask scan;
// blocks [12289, 12545) LayerNorm-1 of inputs -> x.
// ---------------------------------------------------------------------------
__global__ __launch_bounds__(256)
void cvt_w(const float4* __restrict__ wq, const float4* __restrict__ wk,
           const float4* __restrict__ wv, const float4* __restrict__ wo,
           const float4* __restrict__ w1, const float4* __restrict__ w2,
           uint2* __restrict__ oqkv, uint2* __restrict__ oo,
           uint2* __restrict__ o1, uint2* __restrict__ o2,
           const int* __restrict__ mask, int* __restrict__ rank,
           int* __restrict__ idx, int* __restrict__ meta,
           const float* __restrict__ inputs, const float* __restrict__ ln1_a,
           const float* __restrict__ ln1_b, __half* __restrict__ xo)
{
    if (blockIdx.x >= 12289) {   // ---- LayerNorm 1 ----
        ln_rows8(inputs, ln1_a, ln1_b, xo, (long)(blockIdx.x - 12289) * 8);
        return;
    }
    if (blockIdx.x == 12288) {   // ---- mask scan ----
        __shared__ int wsum[8];
        const int tid = threadIdx.x, lane = tid & 31, w = tid >> 5;
        int vals[8], local = 0;
        #pragma unroll
        for (int i = 0; i < 8; i++) { vals[i] = mask[tid * 8 + i] != 0; local += vals[i]; }
        int pre = local;
        #pragma unroll
        for (int o = 1; o < 32; o <<= 1) {
            int t = __shfl_up_sync(0xffffffffu, pre, o);
            if (lane >= o) pre += t;
        }
        if (lane == 31) wsum[w] = pre;
        __syncthreads();
        if (tid == 0) {
            int a = 0;
            #pragma unroll
            for (int i = 0; i < 8; i++) { int t = wsum[i]; wsum[i] = a; a += t; }
            meta[0] = a;
            int pad = (a + 255) & ~255;
            meta[1] = pad < 256 ? 256 : pad;
        }
        __syncthreads();
        int base = wsum[w] + pre - local;
        #pragma unroll
        for (int i = 0; i < 8; i++) {
            const int p = tid * 8 + i;
            if (vals[i]) { rank[p] = base; idx[base] = p; base++; }
            else rank[p] = -1;
        }
        __syncthreads();
        const int cnt = meta[0];
        for (int p = tid; p < S_; p += 256)
            if (p >= cnt) idx[p] = 0;
        return;
    }
    const int i = blockIdx.x * 256 + threadIdx.x;
    const float4* s; uint2* d; int off;
    if      (i <  262144) { s = wq; d = oqkv;          off = i; }
    else if (i <  524288) { s = wk; d = oqkv + 262144; off = i -  262144; }
    else if (i <  786432) { s = wv; d = oqkv + 524288; off = i -  524288; }
    else if (i < 1048576) { s = wo; d = oo;            off = i -  786432; }
    else if (i < 2097152) { s = w1; d = o1;            off = i - 1048576; }
    else                  { s = w2; d = o2;            off = i - 2097152; }
    const float4 v = s[off];
    const __half2 a = __floats2half2_rn(v.x, v.y);
    const __half2 b = __floats2half2_rn(v.z, v.w);
    d[off] = make_uint2(*(uint32_t*)&a, *(uint32_t*)&b);
}

// standalone LN (sublayer 2)
__global__ __launch_bounds__(256)
void ln_kernel(const float* __restrict__ X, const float* __restrict__ ga,
               const float* __restrict__ gb, __half* __restrict__ OH)
{
    ln_rows8(X, ga, gb, OH, (long)blockIdx.x * 8);
}

// ---------------------------------------------------------------------------
// entmax-1.5 stats body, templated on half2-register footprint NH2
// (NH2*64 = row width covered).  half2 Newton + one exact fp32 refinement;
// normalization by exact quadratic extrapolation (f''=2k on fixed support).
// ---------------------------------------------------------------------------
template<int NH2>
__device__ __forceinline__ float2 stats_body(const uint4* __restrict__ p4,
                                             int lane, int nI)
{
    __half2 x2[NH2];
    #pragma unroll
    for (int i = 0; i < NH2 / 4; i++) {
        if (i < nI) {
            const uint4 u = p4[i * 32 + lane];
            const uint32_t* wv = (const uint32_t*)&u;
            #pragma unroll
            for (int c = 0; c < 4; c++) x2[4*i+c] = *(const __half2*)&wv[c];
        } else {
            #pragma unroll
            for (int c = 0; c < 4; c++) x2[4*i+c] = __float2half2_rn(MASKED_X);
        }
    }

    // ---- max ----
    __half2 m2 = x2[0];
    #pragma unroll
    for (int i = 1; i < NH2; i++) m2 = __hmax2(m2, x2[i]);
    float mx = fmaxf(__low2float(m2), __high2float(m2));
    #pragma unroll
    for (int o = 16; o > 0; o >>= 1)
        mx = fmaxf(mx, __shfl_xor_sync(0xffffffffu, mx, o));

    // ---- half2 Newton (approximate, early exit) ----
    float tau = mx - 1.0f;
    #pragma unroll 1
    for (int it = 0; it < 6; it++) {
        const __half2 t2 = __float2half2_rn(tau);
        const __half2 z  = __float2half2_rn(0.f);
        __half2 f2 = z, g2 = z;
        #pragma unroll
        for (int i = 0; i < NH2; i++) {
            const __half2 t = __hmax2(__hsub2(x2[i], t2), z);
            f2 = __hfma2(t, t, f2);
            g2 = __hadd2(g2, t);
        }
        float f = __low2float(f2) + __high2float(f2);
        float g = __low2float(g2) + __high2float(g2);
        #pragma unroll
        for (int o = 16; o > 0; o >>= 1) {
            f += __shfl_xor_sync(0xffffffffu, f, o);
            g += __shfl_xor_sync(0xffffffffu, g, o);
        }
        tau += (f - 1.0f) / (2.0f * g);
        if (f - 1.0f < 5e-3f) break;
    }

    // ---- one exact fp32 pass: f, g, k at tau ----
    float f = 0.f, g = 0.f;
    int k = 0;
    #pragma unroll
    for (int i = 0; i < NH2; i++) {
        const float2 v = __half22float2(x2[i]);
        const float t0 = fmaxf(v.x - tau, 0.f);
        const float t1 = fmaxf(v.y - tau, 0.f);
        f = fmaf(t0, t0, f);
        f = fmaf(t1, t1, f);
        g += t0 + t1;
        k += (t0 > 0.f) + (t1 > 0.f);
    }
    #pragma unroll
    for (int o = 16; o > 0; o >>= 1) {
        f += __shfl_xor_sync(0xffffffffu, f, o);
        g += __shfl_xor_sync(0xffffffffu, g, o);
        k += __shfl_xor_sync(0xffffffffu, k, o);
    }

    // final Newton step + exact quadratic extrapolation to tau1 and tau_q
    const float dtau = (f - 1.0f) / (2.0f * g);
    const float tau1 = tau + dtau;
    const float g1   = g - (float)k * dtau;
    const float f1   = f - 2.0f * g * dtau + (float)k * dtau * dtau;
    const float tq   = __half2float(__float2half_rn(tau1));
    const float d2   = tq - tau1;
    const float fq   = f1 - 2.0f * g1 * d2 + (float)k * d2 * d2;
    return make_float2(tq, 1.0f / fq);
}

// entmax-1.5 stats: warp per row; NH2=16 fast path when cnt_pad <= 1024.
__global__ __launch_bounds__(256)
void entmax_stats(const __half* __restrict__ SX, const int* __restrict__ meta,
                  float2* __restrict__ TAU)
{
    const int wid = threadIdx.x >> 5, lane = threadIdx.x & 31;
    const long row = (long)blockIdx.x * 8 + wid;
    const uint4* p4 = (const uint4*)(SX + row * (long)S_);
    const int nI = meta[1] >> 8;               // 256 halves per warp-iteration

    float2 ts;
    if (nI <= 4) ts = stats_body<16>(p4, lane, nI);
    else         ts = stats_body<32>(p4, lane, nI);
    if (lane == 0) TAU[row] = ts;
}

// ---------------------------------------------------------------------------
// Scores: Q-tile resident; dynamic ntiles over compacted keys; K rows loaded
// indirectly via idx.  Output fp16, cols >= cnt forced to MASKED_X.
// ---------------------------------------------------------------------------
__global__ __launch_bounds__(256, 2)
void scores_mma(const __half* __restrict__ Q, const __half* __restrict__ Km,
                const int* __restrict__ idxp, const int* __restrict__ meta,
                __half* __restrict__ SX, float alpha)
{
    constexpr int LDSB = 144;
    constexpr int ABYTES = 128 * LDSB;
    constexpr int BBYTES = 128 * LDSB;
    constexpr int MI = 4, NJ = 4;   // warp tile 64x32, 8 warps (2x4)

    extern __shared__ char smem[];
    const uint32_t sb = smem_u32(smem);

    const int cnt = meta[0], cnt_pad = meta[1];
    const int tid  = threadIdx.x;
    const int wid  = tid >> 5;
    const int lane = tid & 31;
    const int z     = blockIdx.z;
    const int m0    = blockIdx.y * 128;
    const int nbase = blockIdx.x * 512;
    if (nbase >= cnt_pad) return;
    const int ntiles = min(4, (cnt_pad - nbase) >> 7);
    const int wtm  = (wid >> 2) * 64;
    const int wtn  = (wid & 3) * 32;

    const __half* ap = Q + (long)m0 * D_ + z * 64;

    auto loadB = [&](int t, int buf) {
        #pragma unroll
        for (int it = 0; it < 4; it++) {
            const int ci = tid + it * 256;
            const int r = ci >> 3, q = ci & 7;
            const int col = nbase + t * 128 + r;
            CP16(sb + ABYTES + buf * BBYTES + r * LDSB + q * 16,
                 Km + (long)idxp[col] * D_ + z * 64 + q * 8);
        }
    };

    #pragma unroll
    for (int it = 0; it < 4; it++) {
        const int ci = tid + it * 256;
        const int r = ci >> 3, q = ci & 7;
        CP16(sb + r * LDSB + q * 16, ap + (long)r * D_ + q * 8);
    }
    loadB(0, 0);
    asm volatile("cp.async.commit_group;");
    if (ntiles > 1) loadB(1, 1);
    asm volatile("cp.async.commit_group;");

    #pragma unroll 1
    for (int t = 0; t < ntiles; t++) {
        if (t < ntiles - 1) asm volatile("cp.async.wait_group 1;");
        else                asm volatile("cp.async.wait_group 0;");
        __syncthreads();

        const uint32_t bbase = sb + ABYTES + (t & 1) * BBYTES;

        float acc[MI][NJ][4];
        #pragma unroll
        for (int i = 0; i < MI; i++)
            #pragma unroll
            for (int j = 0; j < NJ; j++)
                #pragma unroll
                for (int r = 0; r < 4; r++) acc[i][j][r] = 0.f;

        #pragma unroll
        for (int ks = 0; ks < 4; ks++) {
            uint32_t afh[MI][4];
            #pragma unroll
            for (int i = 0; i < MI; i++) {
                const int row = wtm + i * 16 + (lane & 15);
                const int kc  = ks * 16 + ((lane >> 4) << 3);
                LDSM4(afh[i], sb + row * LDSB + kc * 2);
            }
            uint32_t bfh[NJ][2];
            #pragma unroll
            for (int jp = 0; jp < NJ / 2; jp++) {
                const int nrow = wtn + jp * 16 + (lane & 7) + ((lane & 16) ? 8 : 0);
                const int kc   = ks * 16 + ((lane & 8) ? 8 : 0);
                uint32_t tt[4];
                LDSM4(tt, bbase + nrow * LDSB + kc * 2);
                bfh[2*jp][0]   = tt[0]; bfh[2*jp][1]   = tt[1];
                bfh[2*jp+1][0] = tt[2]; bfh[2*jp+1][1] = tt[3];
            }
            #pragma unroll
            for (int i = 0; i < MI; i++)
                #pragma unroll
                for (int j = 0; j < NJ; j++)
                    MMA16816(acc[i][j], afh[i], bfh[j]);
        }
        __syncthreads();

        if (t + 2 < ntiles) loadB(t + 2, t & 1);
        asm volatile("cp.async.commit_group;");

        const int n0 = nbase + t * 128;
        __half* outp = SX + (long)z * S_ * S_;
        #pragma unroll
        for (int i = 0; i < MI; i++)
            #pragma unroll
            for (int j = 0; j < NJ; j++) {
                const int colb = n0 + wtn + j * 8 + (lane & 3) * 2;
                const bool v0ok = colb < cnt, v1ok = colb + 1 < cnt;
                #pragma unroll
                for (int h = 0; h < 2; h++) {
                    const int row = m0 + wtm + i * 16 + (lane >> 2) + h * 8;
                    const float v0 = v0ok ? acc[i][j][2*h]   * alpha : MASKED_X;
                    const float v1 = v1ok ? acc[i][j][2*h+1] * alpha : MASKED_X;
                    *(uint32_t*)(outp + (long)row * S_ + colb)
                        = pack2(__float2half_rn(v0), __float2half_rn(v1));
                }
            }
    }
}

// Pure-fp16 warp-MMA GEMM.  C[m,n] = sum_k A[m,k]*B[n,k]  (K-major both)
// MODE: 3 PV (half2 in-register probs via {tau_q, s}, K from meta[1])
//       4 bias+resid -> fp32, 5 bias+relu -> fp16,
//       7 fused QKV (z=0 q, z=1 k, z=2 compacted transposed v via rankp)
// V pad slots [cnt, cnt_pad) are never written; zero-initialized globals and
// prob_tf gives exactly 0 at pad columns, so PV is exact without vpad.
template<int BM, int BN, int WM, int WN, int MODE, int OCC>
__global__ __launch_bounds__((BM/WM)*(BN/WN)*32, OCC)
void gemm_mma(const __half* __restrict__ A, int lda, long zsA,
              const __half* __restrict__ B, int ldb, long zsB,
              int K, const int* __restrict__ meta, const int* __restrict__ rankp,
              float* __restrict__ Cf, long zsC, int ldc,
              __half* __restrict__ Chi, __half* __restrict__ Chi2,
              __half* __restrict__ Chi3,
              const float* __restrict__ bias, const float* __restrict__ bias2,
              const float* __restrict__ bias3,
              const float* __restrict__ resid, float alpha)
{
    constexpr int BK = 64;
    constexpr int WARPS_M = BM / WM, WARPS_N = BN / WN;
    constexpr int THREADS = WARPS_M * WARPS_N * 32;
    constexpr int MI = WM / 16, NJ = WN / 8;
    constexpr int LDSB   = 144;
    constexpr int ABYTES = BM * LDSB;
    constexpr int BBYTES = BN * LDSB;
    constexpr int STAGE  = ABYTES + BBYTES;

    extern __shared__ char smem[];
    const uint32_t sb = smem_u32(smem);

    const int tid  = threadIdx.x;
    const int wid  = tid >> 5;
    const int lane = tid & 31;
    const int z    = blockIdx.z;
    const int m0   = blockIdx.y * BM;
    const int n0   = blockIdx.x * BN;
    const int wtm  = (wid / WARPS_N) * WM;
    const int wtn  = (wid % WARPS_N) * WN;

    const int Keff = (MODE == 3) ? meta[1] : K;

    const __half* ap = A + (long)z * zsA + (long)m0 * lda;
    const __half* bp = B + (long)z * zsB + (long)n0 * ldb;

    uint32_t tq2[MI][2], ss2[MI][2];
    if (MODE == 3) {
        const float2* taup = (const float2*)bias;
        #pragma unroll
        for (int i = 0; i < MI; i++) {
            const int r = m0 + wtm + i * 16 + (lane >> 2);
            const float2 a0 = taup[z * S_ + r];
            const float2 a1 = taup[z * S_ + r + 8];
            const __half2 t0 = __float2half2_rn(a0.x), s0 = __float2half2_rn(a0.y);
            const __half2 t1 = __float2half2_rn(a1.x), s1 = __float2half2_rn(a1.y);
            tq2[i][0] = *(const uint32_t*)&t0; ss2[i][0] = *(const uint32_t*)&s0;
            tq2[i][1] = *(const uint32_t*)&t1; ss2[i][1] = *(const uint32_t*)&s1;
        }
    }

    float acc[MI][NJ][4];
    #pragma unroll
    for (int i = 0; i < MI; i++)
        #pragma unroll
        for (int j = 0; j < NJ; j++)
            #pragma unroll
            for (int r = 0; r < 4; r++) acc[i][j][r] = 0.f;

    const int nc = Keff / BK;

    auto load_stage = [&](int buf, int c) {
        const uint32_t base = sb + buf * STAGE;
        const int k0 = c * BK;
        #pragma unroll
        for (int it = 0; it < (BM * 8) / THREADS; it++) {
            const int ci = tid + it * THREADS;
            const int r = ci >> 3, q = ci & 7;
            CP16(base + r * LDSB + q * 16, ap + (long)r * lda + k0 + q * 8);
        }
        #pragma unroll
        for (int it = 0; it < (BN * 8) / THREADS; it++) {
            const int ci = tid + it * THREADS;
            const int r = ci >> 3, q = ci & 7;
            CP16(base + ABYTES + r * LDSB + q * 16,
                 bp + (long)r * ldb + k0 + q * 8);
        }
        asm volatile("cp.async.commit_group;");
    };

    load_stage(0, 0);

    for (int c = 0; c < nc; c++) {
        if (c + 1 < nc) {
            load_stage((c + 1) & 1, c + 1);
            asm volatile("cp.async.wait_group 1;");
        } else {
            asm volatile("cp.async.wait_group 0;");
        }
        __syncthreads();

        const uint32_t base = sb + (c & 1) * STAGE;
        #pragma unroll
        for (int ks = 0; ks < 4; ks++) {
            uint32_t afh[MI][4];
            #pragma unroll
            for (int i = 0; i < MI; i++) {
                const int row = wtm + i * 16 + (lane & 15);
                const int kc  = ks * 16 + ((lane >> 4) << 3);
                LDSM4(afh[i], base + row * LDSB + kc * 2);
                if (MODE == 3) {
                    afh[i][0] = prob_tf(afh[i][0], tq2[i][0], ss2[i][0]);
                    afh[i][2] = prob_tf(afh[i][2], tq2[i][0], ss2[i][0]);
                    afh[i][1] = prob_tf(afh[i][1], tq2[i][1], ss2[i][1]);
                    afh[i][3] = prob_tf(afh[i][3], tq2[i][1], ss2[i][1]);
                }
            }
            uint32_t bfh[NJ][2];
            #pragma unroll
            for (int jp = 0; jp < NJ / 2; jp++) {
                const int nrow = wtn + jp * 16 + (lane & 7) + ((lane & 16) ? 8 : 0);
                const int kc   = ks * 16 + ((lane & 8) ? 8 : 0);
                uint32_t t[4];
                LDSM4(t, base + ABYTES + nrow * LDSB + kc * 2);
                bfh[2*jp][0]   = t[0]; bfh[2*jp][1]   = t[1];
                bfh[2*jp+1][0] = t[2]; bfh[2*jp+1][1] = t[3];
            }
            #pragma unroll
            for (int i = 0; i < MI; i++)
                #pragma unroll
                for (int j = 0; j < NJ; j++)
                    MMA16816(acc[i][j], afh[i], bfh[j]);
        }
        __syncthreads();
    }

    // ---- epilogue ----
    #pragma unroll
    for (int i = 0; i < MI; i++)
        #pragma unroll
        for (int j = 0; j < NJ; j++) {
            const int colb = n0 + wtn + j * 8 + (lane & 3) * 2;
            #pragma unroll
            for (int h = 0; h < 2; h++) {
                const int row = m0 + wtm + i * 16 + (lane >> 2) + h * 8;
                float v0 = acc[i][j][2*h], v1 = acc[i][j][2*h+1];
                if (MODE == 3) {
                    *(uint32_t*)(Chi + (long)row * ldc + z * 64 + colb)
                        = pack2(__float2half_rn(v0), __float2half_rn(v1));
                } else if (MODE == 4) {
                    const long idx = (long)row * ldc + colb;
                    const float2 b2 = *(const float2*)(bias + colb);
                    const float2 r2 = *(const float2*)(resid + idx);
                    *(float2*)(Cf + idx) = make_float2(v0 + b2.x + r2.x,
                                                       v1 + b2.y + r2.y);
                } else if (MODE == 5) {
                    const float2 b2 = *(const float2*)(bias + colb);
                    v0 = fmaxf(v0 + b2.x, 0.f); v1 = fmaxf(v1 + b2.y, 0.f);
                    *(uint32_t*)(Chi + (long)row * ldc + colb)
                        = pack2(__float2half_rn(v0), __float2half_rn(v1));
                } else {  // MODE 7
                    const float* bpt = (z == 0) ? bias : (z == 1 ? bias2 : bias3);
                    const float2 b2 = *(const float2*)(bpt + colb);
                    v0 += b2.x; v1 += b2.y;
                    if (z == 0) {
                        *(uint32_t*)(Chi + (long)row * ldc + colb)
                            = pack2(__float2half_rn(v0), __float2half_rn(v1));
                    } else if (z == 1) {
                        *(uint32_t*)(Chi2 + (long)row * ldc + colb)
                            = pack2(__float2half_rn(v0), __float2half_rn(v1));
                    } else {
                        const int rk = rankp[row];
                        if (rk >= 0) {
                            Chi3[(long)colb * S_ + rk]       = __float2half_rn(v0);
                            Chi3[(long)(colb + 1) * S_ + rk] = __float2half_rn(v1);
                        }
                    }
                }
            }
        }
}

template<typename T>
static T* sym(const void* s) {
    void* p = nullptr;
    cudaGetSymbolAddress(&p, s);
    return (T*)p;
}

extern "C" void kernel_launch(void* const* d_in, const int* in_sizes, int n_in,
                              void* d_out, int out_size)
{
    const float* inputs = (const float*)d_in[0];
    const int*   mask   = (const int*)  d_in[1];
    const float* wq = (const float*)d_in[2];  const float* bq = (const float*)d_in[3];
    const float* wk = (const float*)d_in[4];  const float* bk = (const float*)d_in[5];
    const float* wv = (const float*)d_in[6];  const float* bv = (const float*)d_in[7];
    const float* wo = (const float*)d_in[8];  const float* bo = (const float*)d_in[9];
    const float* ln1_a = (const float*)d_in[10]; const float* ln1_b = (const float*)d_in[11];
    const float* w1 = (const float*)d_in[12]; const float* b1 = (const float*)d_in[13];
    const float* w2 = (const float*)d_in[14]; const float* b2 = (const float*)d_in[15];
    const float* ln2_a = (const float*)d_in[16]; const float* ln2_b = (const float*)d_in[17];
    float* out = (float*)d_out;

    __half *sx  = sym<__half>(g_sx);
    float2 *tau = sym<float2>(g_tau);
    __half *x   = sym<__half>(g_x);
    __half *q   = sym<__half>(g_q);
    __half *k   = sym<__half>(g_k);
    __half *vt  = sym<__half>(g_vt);
    __half *at  = sym<__half>(g_at);
    float  *y   = sym<float>(g_y);
    __half *h1  = sym<__half>(g_h1);
    __half *wqkv = sym<__half>(g_wqkv);
    __half *woh = sym<__half>(g_wo);
    __half *w1h = sym<__half>(g_w1), *w2h = sym<__half>(g_w2);
    int *idx  = sym<int>(g_idx);
    int *rank = sym<int>(g_rank);
    int *meta = sym<int>(g_meta);

    constexpr int SM_GP = 2 * (128 + 64) * 144;   // 55296
    constexpr int SM_SC = 3 * 128 * 144;          // 55296

    cudaFuncSetAttribute((const void*)gemm_mma<128,64,32,32,7,3>,
                         cudaFuncAttributeMaxDynamicSharedMemorySize, SM_GP);
    cudaFuncSetAttribute((const void*)gemm_mma<128,64,32,32,4,3>,
                         cudaFuncAttributeMaxDynamicSharedMemorySize, SM_GP);
    cudaFuncSetAttribute((const void*)gemm_mma<128,64,32,32,5,3>,
                         cudaFuncAttributeMaxDynamicSharedMemorySize, SM_GP);
    cudaFuncSetAttribute((const void*)gemm_mma<128,64,32,32,3,3>,
                         cudaFuncAttributeMaxDynamicSharedMemorySize, SM_GP);
    cudaFuncSetAttribute((const void*)scores_mma,
                         cudaFuncAttributeMaxDynamicSharedMemorySize, SM_SC);

    const dim3 blk256(256);

    // weights -> fp16 + mask scan + LN1, one launch
    cvt_w<<<12545, blk256>>>((const float4*)wq, (const float4*)wk, (const float4*)wv,
                             (const float4*)wo, (const float4*)w1, (const float4*)w2,
                             (uint2*)wqkv, (uint2*)woh, (uint2*)w1h, (uint2*)w2h,
                             mask, rank, idx, meta,
                             inputs, ln1_a, ln1_b, x);

    // fused QKV: V epilogue writes compacted transposed V
    gemm_mma<128,64,32,32,7,3><<<dim3(D_/64, S_/128, 3), blk256, SM_GP>>>(
        x, D_, 0, wqkv, D_, (long)D_ * D_, D_, nullptr, rank,
        nullptr, 0, D_, q, k, vt,
        bq, bk, bv, nullptr, 0.f);

    // scores over compacted keys; alpha = 0.125 * 0.5 = 0.0625
    scores_mma<<<dim3(4, S_/128, H_), blk256, SM_SC>>>(q, k, idx, meta, sx, 0.0625f);

    // entmax stats: half2 Newton + fp32 refinement, width-specialized
    entmax_stats<<<H_ * S_ / 8, blk256>>>(sx, meta, tau);

    // PV: half2 in-register probs, K = cnt_pad from meta
    gemm_mma<128,64,32,32,3,3><<<dim3(1, S_/128, H_), blk256, SM_GP>>>(
        sx, S_, (long)S_ * S_, vt, S_, (long)64 * S_, 0, meta, nullptr,
        nullptr, 0, D_, at, nullptr, nullptr,
        (const float*)tau, nullptr, nullptr, nullptr, 0.f);

    // Wo + residual -> y (fp32)
    gemm_mma<128,64,32,32,4,3><<<dim3(D_/64, S_/128), blk256, SM_GP>>>(
        at, D_, 0, woh, D_, 0, D_, nullptr, nullptr,
        y, 0, D_, nullptr, nullptr, nullptr,
        bo, nullptr, nullptr, inputs, 0.f);

    ln_kernel<<<S_ / 8, blk256>>>(y, ln2_a, ln2_b, x);

    // FFN1: relu(x @ w1^T + b1) -> fp16
    gemm_mma<128,64,32,32,5,3><<<dim3(DFF_/64, S_/128), blk256, SM_GP>>>(
        x, D_, 0, w1h, D_, 0, D_, nullptr, nullptr,
        nullptr, 0, DFF_, h1, nullptr, nullptr,
        b1, nullptr, nullptr, nullptr, 0.f);

    // FFN2 + residual -> out
    gemm_mma<128,64,32,32,4,3><<<dim3(D_/64, S_/128), blk256, SM_GP>>>(
        h1, DFF_, 0, w2h, DFF_, 0, DFF_, nullptr, nullptr,
        out, 0, D_, nullptr, nullptr, nullptr,
        b2, nullptr, nullptr, y, 0.f);
}

// round 17
// speedup vs baseline: 1.0519x; 1.0519x over previous
#include <cuda_runtime.h>
#include <cuda_fp16.h>
#include <cstdint>

#define S_   2048
#define D_   1024
#define H_   16
#define HD_  64
#define DFF_ 4096

__device__ __align__(16) __half g_sx [(long)H_ * S_ * S_];   // fp16 compact scores
__device__ __align__(16) float2 g_tau[H_ * S_];              // per-row {tau_q, scale}
__device__ __align__(16) __half g_x  [S_ * D_];
__device__ __align__(16) __half g_q  [S_ * D_];
__device__ __align__(16) __half g_k  [S_ * D_];
__device__ __align__(16) __half g_vt [S_ * D_];              // [h][64][slot] compacted
__device__ __align__(16) __half g_at [S_ * D_];
__device__ __align__(16) float  g_y  [S_ * D_];
__device__ __align__(16) __half g_h1 [S_ * DFF_];
__device__ __align__(16) __half g_wqkv[3 * D_ * D_];
__device__ __align__(16) __half g_wo[D_ * D_];
__device__ __align__(16) __half g_w1[DFF_ * D_], g_w2[D_ * DFF_];
__device__ int g_idx [S_];     // compact slot -> token
__device__ int g_rank[S_];     // token -> compact slot, -1 if masked
__device__ int g_meta[2];      // {cnt, cnt_pad}

#define MASKED_X (-30000.0f)

__device__ __forceinline__ uint32_t smem_u32(const void* p) {
    uint32_t a;
    asm("{ .reg .u64 t; cvta.to.shared.u64 t, %1; cvt.u32.u64 %0, t; }"
        : "=r"(a) : "l"(p));
    return a;
}

#define CP16(dst, src) \
    asm volatile("cp.async.cg.shared.global [%0], [%1], 16;" \
                 :: "r"(dst), "l"(src))

#define LDSM4(r, addr) \
    asm volatile("ldmatrix.sync.aligned.m8n8.x4.shared.b16 {%0,%1,%2,%3}, [%4];" \
                 : "=r"((r)[0]), "=r"((r)[1]), "=r"((r)[2]), "=r"((r)[3]) \
                 : "r"(addr))

#define MMA16816(d, a, b) \
    asm volatile("mma.sync.aligned.m16n8k16.row.col.f32.f16.f16.f32 " \
                 "{%0,%1,%2,%3}, {%4,%5,%6,%7}, {%8,%9}, {%0,%1,%2,%3};" \
                 : "+f"((d)[0]), "+f"((d)[1]), "+f"((d)[2]), "+f"((d)[3]) \
                 : "r"((a)[0]), "r"((a)[1]), "r"((a)[2]), "r"((a)[3]), \
                   "r"((b)[0]), "r"((b)[1]))

__device__ __forceinline__ uint32_t pack2(__half a, __half b) {
    __half2 h; h.x = a; h.y = b;
    return *(uint32_t*)&h;
}

// fp16 scores -> scaled probs, all-half2: p = s * relu(x - tau_q)^2
__device__ __forceinline__ uint32_t prob_tf(uint32_t u, uint32_t tq2, uint32_t s2) {
    const __half2 z = __float2half2_rn(0.f);
    __half2 t = __hmax2(__hsub2(*(__half2*)&u, *(__half2*)&tq2), z);
    t = __hmul2(__hmul2(t, t), *(__half2*)&s2);
    return *(const uint32_t*)&t;
}

// warp-per-row LayerNorm body (8 rows per 256-thread CTA)
__device__ __forceinline__ void ln_rows8(const float* __restrict__ X,
                                         const float* __restrict__ ga,
                                         const float* __restrict__ gb,
                                         __half* __restrict__ OH, long rowbase)
{
    const int w = threadIdx.x >> 5, lane = threadIdx.x & 31;
    const long row = rowbase + w;
    const float4* x4 = (const float4*)(X + row * D_);

    float4 v[8];
    float s = 0.f, sq = 0.f;
    #pragma unroll
    for (int i = 0; i < 8; i++) {
        v[i] = x4[i * 32 + lane];
        s  += v[i].x + v[i].y + v[i].z + v[i].w;
        sq += v[i].x*v[i].x + v[i].y*v[i].y + v[i].z*v[i].z + v[i].w*v[i].w;
    }
    #pragma unroll
    for (int o = 16; o > 0; o >>= 1) {
        s  += __shfl_xor_sync(0xffffffffu, s,  o);
        sq += __shfl_xor_sync(0xffffffffu, sq, o);
    }
    const float mu  = s * (1.0f / D_);
    const float var = fmaxf((sq - mu * mu * (float)D_) * (1.0f / (D_ - 1)), 0.0f);
    const float inv = 1.0f / (sqrtf(var) + 1e-6f);

    const float4* a4 = (const float4*)ga;
    const float4* b4 = (const float4*)gb;
    uint2* dst = (uint2*)(OH + row * D_);
    #pragma unroll
    for (int i = 0; i < 8; i++) {
        const float4 a = a4[i * 32 + lane];
        const float4 b = b4[i * 32 + lane];
        const float o0 = (v[i].x - mu) * inv * a.x + b.x;
        const float o1 = (v[i].y - mu) * inv * a.y + b.y;
        const float o2 = (v[i].z - mu) * inv * a.z + b.z;
        const float o3 = (v[i].w - mu) * inv * a.w + b.w;
        dst[i * 32 + lane] = make_uint2(pack2(__float2half_rn(o0), __float2half_rn(o1)),
                                        pack2(__float2half_rn(o2), __float2half_rn(o3)));
    }
}

// ---------------------------------------------------------------------------
// cvt_w: blocks [0,12288) weights->fp16; block 12288 mask scan;
// blocks [12289, 12545) LayerNorm-1 of inputs -> x.
// ---------------------------------------------------------------------------
__global__ __launch_bounds__(256)
void cvt_w(const float4* __restrict__ wq, const float4* __restrict__ wk,
           const float4* __restrict__ wv, const float4* __restrict__ wo,
           const float4* __restrict__ w1, const float4* __restrict__ w2,
           uint2* __restrict__ oqkv, uint2* __restrict__ oo,
           uint2* __restrict__ o1, uint2* __restrict__ o2,
           const int* __restrict__ mask, int* __restrict__ rank,
           int* __restrict__ idx, int* __restrict__ meta,
           const float* __restrict__ inputs, const float* __restrict__ ln1_a,
           const float* __restrict__ ln1_b, __half* __restrict__ xo)
{
    if (blockIdx.x >= 12289) {   // ---- LayerNorm 1 ----
        ln_rows8(inputs, ln1_a, ln1_b, xo, (long)(blockIdx.x - 12289) * 8);
        return;
    }
    if (blockIdx.x == 12288) {   // ---- mask scan ----
        __shared__ int wsum[8];
        const int tid = threadIdx.x, lane = tid & 31, w = tid >> 5;
        int vals[8], local = 0;
        #pragma unroll
        for (int i = 0; i < 8; i++) { vals[i] = mask[tid * 8 + i] != 0; local += vals[i]; }
        int pre = local;
        #pragma unroll
        for (int o = 1; o < 32; o <<= 1) {
            int t = __shfl_up_sync(0xffffffffu, pre, o);
            if (lane >= o) pre += t;
        }
        if (lane == 31) wsum[w] = pre;
        __syncthreads();
        if (tid == 0) {
            int a = 0;
            #pragma unroll
            for (int i = 0; i < 8; i++) { int t = wsum[i]; wsum[i] = a; a += t; }
            meta[0] = a;
            int pad = (a + 255) & ~255;
            meta[1] = pad < 256 ? 256 : pad;
        }
        __syncthreads();
        int base = wsum[w] + pre - local;
        #pragma unroll
        for (int i = 0; i < 8; i++) {
            const int p = tid * 8 + i;
            if (vals[i]) { rank[p] = base; idx[base] = p; base++; }
            else rank[p] = -1;
        }
        __syncthreads();
        const int cnt = meta[0];
        for (int p = tid; p < S_; p += 256)
            if (p >= cnt) idx[p] = 0;
        return;
    }
    const int i = blockIdx.x * 256 + threadIdx.x;
    const float4* s; uint2* d; int off;
    if      (i <  262144) { s = wq; d = oqkv;          off = i; }
    else if (i <  524288) { s = wk; d = oqkv + 262144; off = i -  262144; }
    else if (i <  786432) { s = wv; d = oqkv + 524288; off = i -  524288; }
    else if (i < 1048576) { s = wo; d = oo;            off = i -  786432; }
    else if (i < 2097152) { s = w1; d = o1;            off = i - 1048576; }
    else                  { s = w2; d = o2;            off = i - 2097152; }
    const float4 v = s[off];
    const __half2 a = __floats2half2_rn(v.x, v.y);
    const __half2 b = __floats2half2_rn(v.z, v.w);
    d[off] = make_uint2(*(uint32_t*)&a, *(uint32_t*)&b);
}

// standalone LN (sublayer 2)
__global__ __launch_bounds__(256)
void ln_kernel(const float* __restrict__ X, const float* __restrict__ ga,
               const float* __restrict__ gb, __half* __restrict__ OH)
{
    ln_rows8(X, ga, gb, OH, (long)blockIdx.x * 8);
}

// ---------------------------------------------------------------------------
// entmax-1.5 stats body, templated on half2-register footprint NH2
// (NH2*64 = row width covered).  half2 Newton + one exact fp32 refinement;
// normalization by exact quadratic extrapolation (f''=2k on fixed support).
// ---------------------------------------------------------------------------
template<int NH2>
__device__ __forceinline__ float2 stats_body(const uint4* __restrict__ p4,
                                             int lane, int nI)
{
    __half2 x2[NH2];
    #pragma unroll
    for (int i = 0; i < NH2 / 4; i++) {
        if (i < nI) {
            const uint4 u = p4[i * 32 + lane];
            const uint32_t* wv = (const uint32_t*)&u;
            #pragma unroll
            for (int c = 0; c < 4; c++) x2[4*i+c] = *(const __half2*)&wv[c];
        } else {
            #pragma unroll
            for (int c = 0; c < 4; c++) x2[4*i+c] = __float2half2_rn(MASKED_X);
        }
    }

    // ---- max ----
    __half2 m2 = x2[0];
    #pragma unroll
    for (int i = 1; i < NH2; i++) m2 = __hmax2(m2, x2[i]);
    float mx = fmaxf(__low2float(m2), __high2float(m2));
    #pragma unroll
    for (int o = 16; o > 0; o >>= 1)
        mx = fmaxf(mx, __shfl_xor_sync(0xffffffffu, mx, o));

    // ---- half2 Newton (approximate, early exit) ----
    float tau = mx - 1.0f;
    #pragma unroll 1
    for (int it = 0; it < 6; it++) {
        const __half2 t2 = __float2half2_rn(tau);
        const __half2 z  = __float2half2_rn(0.f);
        __half2 f2 = z, g2 = z;
        #pragma unroll
        for (int i = 0; i < NH2; i++) {
            const __half2 t = __hmax2(__hsub2(x2[i], t2), z);
            f2 = __hfma2(t, t, f2);
            g2 = __hadd2(g2, t);
        }
        float f = __low2float(f2) + __high2float(f2);
        float g = __low2float(g2) + __high2float(g2);
        #pragma unroll
        for (int o = 16; o > 0; o >>= 1) {
            f += __shfl_xor_sync(0xffffffffu, f, o);
            g += __shfl_xor_sync(0xffffffffu, g, o);
        }
        tau += (f - 1.0f) / (2.0f * g);
        if (f - 1.0f < 5e-3f) break;
    }

    // ---- one exact fp32 pass: f, g, k at tau ----
    float f = 0.f, g = 0.f;
    int k = 0;
    #pragma unroll
    for (int i = 0; i < NH2; i++) {
        const float2 v = __half22float2(x2[i]);
        const float t0 = fmaxf(v.x - tau, 0.f);
        const float t1 = fmaxf(v.y - tau, 0.f);
        f = fmaf(t0, t0, f);
        f = fmaf(t1, t1, f);
        g += t0 + t1;
        k += (t0 > 0.f) + (t1 > 0.f);
    }
    #pragma unroll
    for (int o = 16; o > 0; o >>= 1) {
        f += __shfl_xor_sync(0xffffffffu, f, o);
        g += __shfl_xor_sync(0xffffffffu, g, o);
        k += __shfl_xor_sync(0xffffffffu, k, o);
    }

    // final Newton step + exact quadratic extrapolation to tau1 and tau_q
    const float dtau = (f - 1.0f) / (2.0f * g);
    const float tau1 = tau + dtau;
    const float g1   = g - (float)k * dtau;
    const float f1   = f - 2.0f * g * dtau + (float)k * dtau * dtau;
    const float tq   = __half2float(__float2half_rn(tau1));
    const float d2   = tq - tau1;
    const float fq   = f1 - 2.0f * g1 * d2 + (float)k * d2 * d2;
    return make_float2(tq, 1.0f / fq);
}

// entmax-1.5 stats: warp per row; register footprint matched to cnt_pad.
// nI = cnt_pad/256 in {1..8}; cnt ~ Binomial(2048, 1/2) => nI is 4 or 5
// in practice (cnt_pad 1024 or 1280); 6 and 8 retained for safety.
__global__ __launch_bounds__(256)
void entmax_stats(const __half* __restrict__ SX, const int* __restrict__ meta,
                  float2* __restrict__ TAU)
{
    const int wid = threadIdx.x >> 5, lane = threadIdx.x & 31;
    const long row = (long)blockIdx.x * 8 + wid;
    const uint4* p4 = (const uint4*)(SX + row * (long)S_);
    const int nI = meta[1] >> 8;               // 256 halves per warp-iteration

    float2 ts;
    if      (nI <= 4) ts = stats_body<16>(p4, lane, nI);
    else if (nI == 5) ts = stats_body<20>(p4, lane, nI);
    else if (nI == 6) ts = stats_body<24>(p4, lane, nI);
    else              ts = stats_body<32>(p4, lane, nI);
    if (lane == 0) TAU[row] = ts;
}

// ---------------------------------------------------------------------------
// Scores: Q-tile resident; dynamic ntiles over compacted keys; K rows loaded
// indirectly via idx.  Output fp16, cols >= cnt forced to MASKED_X.
// ---------------------------------------------------------------------------
__global__ __launch_bounds__(256, 2)
void scores_mma(const __half* __restrict__ Q, const __half* __restrict__ Km,
                const int* __restrict__ idxp, const int* __restrict__ meta,
                __half* __restrict__ SX, float alpha)
{
    constexpr int LDSB = 144;
    constexpr int ABYTES = 128 * LDSB;
    constexpr int BBYTES = 128 * LDSB;
    constexpr int MI = 4, NJ = 4;   // warp tile 64x32, 8 warps (2x4)

    extern __shared__ char smem[];
    const uint32_t sb = smem_u32(smem);

    const int cnt = meta[0], cnt_pad = meta[1];
    const int tid  = threadIdx.x;
    const int wid  = tid >> 5;
    const int lane = tid & 31;
    const int z     = blockIdx.z;
    const int m0    = blockIdx.y * 128;
    const int nbase = blockIdx.x * 512;
    if (nbase >= cnt_pad) return;
    const int ntiles = min(4, (cnt_pad - nbase) >> 7);
    const int wtm  = (wid >> 2) * 64;
    const int wtn  = (wid & 3) * 32;

    const __half* ap = Q + (long)m0 * D_ + z * 64;

    auto loadB = [&](int t, int buf) {
        #pragma unroll
        for (int it = 0; it < 4; it++) {
            const int ci = tid + it * 256;
            const int r = ci >> 3, q = ci & 7;
            const int col = nbase + t * 128 + r;
            CP16(sb + ABYTES + buf * BBYTES + r * LDSB + q * 16,
                 Km + (long)idxp[col] * D_ + z * 64 + q * 8);
        }
    };

    #pragma unroll
    for (int it = 0; it < 4; it++) {
        const int ci = tid + it * 256;
        const int r = ci >> 3, q = ci & 7;
        CP16(sb + r * LDSB + q * 16, ap + (long)r * D_ + q * 8);
    }
    loadB(0, 0);
    asm volatile("cp.async.commit_group;");
    if (ntiles > 1) loadB(1, 1);
    asm volatile("cp.async.commit_group;");

    #pragma unroll 1
    for (int t = 0; t < ntiles; t++) {
        if (t < ntiles - 1) asm volatile("cp.async.wait_group 1;");
        else                asm volatile("cp.async.wait_group 0;");
        __syncthreads();

        const uint32_t bbase = sb + ABYTES + (t & 1) * BBYTES;

        float acc[MI][NJ][4];
        #pragma unroll
        for (int i = 0; i < MI; i++)
            #pragma unroll
            for (int j = 0; j < NJ; j++)
                #pragma unroll
                for (int r = 0; r < 4; r++) acc[i][j][r] = 0.f;

        #pragma unroll
        for (int ks = 0; ks < 4; ks++) {
            uint32_t afh[MI][4];
            #pragma unroll
            for (int i = 0; i < MI; i++) {
                const int row = wtm + i * 16 + (lane & 15);
                const int kc  = ks * 16 + ((lane >> 4) << 3);
                LDSM4(afh[i], sb + row * LDSB + kc * 2);
            }
            uint32_t bfh[NJ][2];
            #pragma unroll
            for (int jp = 0; jp < NJ / 2; jp++) {
                const int nrow = wtn + jp * 16 + (lane & 7) + ((lane & 16) ? 8 : 0);
                const int kc   = ks * 16 + ((lane & 8) ? 8 : 0);
                uint32_t tt[4];
                LDSM4(tt, bbase + nrow * LDSB + kc * 2);
                bfh[2*jp][0]   = tt[0]; bfh[2*jp][1]   = tt[1];
                bfh[2*jp+1][0] = tt[2]; bfh[2*jp+1][1] = tt[3];
            }
            #pragma unroll
            for (int i = 0; i < MI; i++)
                #pragma unroll
                for (int j = 0; j < NJ; j++)
                    MMA16816(acc[i][j], afh[i], bfh[j]);
        }
        __syncthreads();

        if (t + 2 < ntiles) loadB(t + 2, t & 1);
        asm volatile("cp.async.commit_group;");

        const int n0 = nbase + t * 128;
        __half* outp = SX + (long)z * S_ * S_;
        #pragma unroll
        for (int i = 0; i < MI; i++)
            #pragma unroll
            for (int j = 0; j < NJ; j++) {
                const int colb = n0 + wtn + j * 8 + (lane & 3) * 2;
                const bool v0ok = colb < cnt, v1ok = colb + 1 < cnt;
                #pragma unroll
                for (int h = 0; h < 2; h++) {
                    const int row = m0 + wtm + i * 16 + (lane >> 2) + h * 8;
                    const float v0 = v0ok ? acc[i][j][2*h]   * alpha : MASKED_X;
                    const float v1 = v1ok ? acc[i][j][2*h+1] * alpha : MASKED_X;
                    *(uint32_t*)(outp + (long)row * S_ + colb)
                        = pack2(__float2half_rn(v0), __float2half_rn(v1));
                }
            }
    }
}

// Pure-fp16 warp-MMA GEMM.  C[m,n] = sum_k A[m,k]*B[n,k]  (K-major both)
// MODE: 3 PV (half2 in-register probs via {tau_q, s}, K from meta[1])
//       4 bias+resid -> fp32, 5 bias+relu -> fp16,
//       7 fused QKV (z=0 q, z=1 k, z=2 compacted transposed v via rankp)
// V pad slots [cnt, cnt_pad) are never written; zero-initialized globals and
// prob_tf gives exactly 0 at pad columns, so PV is exact without vpad.
template<int BM, int BN, int WM, int WN, int MODE, int OCC>
__global__ __launch_bounds__((BM/WM)*(BN/WN)*32, OCC)
void gemm_mma(const __half* __restrict__ A, int lda, long zsA,
              const __half* __restrict__ B, int ldb, long zsB,
              int K, const int* __restrict__ meta, const int* __restrict__ rankp,
              float* __restrict__ Cf, long zsC, int ldc,
              __half* __restrict__ Chi, __half* __restrict__ Chi2,
              __half* __restrict__ Chi3,
              const float* __restrict__ bias, const float* __restrict__ bias2,
              const float* __restrict__ bias3,
              const float* __restrict__ resid, float alpha)
{
    constexpr int BK = 64;
    constexpr int WARPS_M = BM / WM, WARPS_N = BN / WN;
    constexpr int THREADS = WARPS_M * WARPS_N * 32;
    constexpr int MI = WM / 16, NJ = WN / 8;
    constexpr int LDSB   = 144;
    constexpr int ABYTES = BM * LDSB;
    constexpr int BBYTES = BN * LDSB;
    constexpr int STAGE  = ABYTES + BBYTES;

    extern __shared__ char smem[];
    const uint32_t sb = smem_u32(smem);

    const int tid  = threadIdx.x;
    const int wid  = tid >> 5;
    const int lane = tid & 31;
    const int z    = blockIdx.z;
    const int m0   = blockIdx.y * BM;
    const int n0   = blockIdx.x * BN;
    const int wtm  = (wid / WARPS_N) * WM;
    const int wtn  = (wid % WARPS_N) * WN;

    const int Keff = (MODE == 3) ? meta[1] : K;

    const __half* ap = A + (long)z * zsA + (long)m0 * lda;
    const __half* bp = B + (long)z * zsB + (long)n0 * ldb;

    uint32_t tq2[MI][2], ss2[MI][2];
    if (MODE == 3) {
        const float2* taup = (const float2*)bias;
        #pragma unroll
        for (int i = 0; i < MI; i++) {
            const int r = m0 + wtm + i * 16 + (lane >> 2);
            const float2 a0 = taup[z * S_ + r];
            const float2 a1 = taup[z * S_ + r + 8];
            const __half2 t0 = __float2half2_rn(a0.x), s0 = __float2half2_rn(a0.y);
            const __half2 t1 = __float2half2_rn(a1.x), s1 = __float2half2_rn(a1.y);
            tq2[i][0] = *(const uint32_t*)&t0; ss2[i][0] = *(const uint32_t*)&s0;
            tq2[i][1] = *(const uint32_t*)&t1; ss2[i][1] = *(const uint32_t*)&s1;
        }
    }

    float acc[MI][NJ][4];
    #pragma unroll
    for (int i = 0; i < MI; i++)
        #pragma unroll
        for (int j = 0; j < NJ; j++)
            #pragma unroll
            for (int r = 0; r < 4; r++) acc[i][j][r] = 0.f;

    const int nc = Keff / BK;

    auto load_stage = [&](int buf, int c) {
        const uint32_t base = sb + buf * STAGE;
        const int k0 = c * BK;
        #pragma unroll
        for (int it = 0; it < (BM * 8) / THREADS; it++) {
            const int ci = tid + it * THREADS;
            const int r = ci >> 3, q = ci & 7;
            CP16(base + r * LDSB + q * 16, ap + (long)r * lda + k0 + q * 8);
        }
        #pragma unroll
        for (int it = 0; it < (BN * 8) / THREADS; it++) {
            const int ci = tid + it * THREADS;
            const int r = ci >> 3, q = ci & 7;
            CP16(base + ABYTES + r * LDSB + q * 16,
                 bp + (long)r * ldb + k0 + q * 8);
        }
        asm volatile("cp.async.commit_group;");
    };

    load_stage(0, 0);

    for (int c = 0; c < nc; c++) {
        if (c + 1 < nc) {
            load_stage((c + 1) & 1, c + 1);
            asm volatile("cp.async.wait_group 1;");
        } else {
            asm volatile("cp.async.wait_group 0;");
        }
        __syncthreads();

        const uint32_t base = sb + (c & 1) * STAGE;
        #pragma unroll
        for (int ks = 0; ks < 4; ks++) {
            uint32_t afh[MI][4];
            #pragma unroll
            for (int i = 0; i < MI; i++) {
                const int row = wtm + i * 16 + (lane & 15);
                const int kc  = ks * 16 + ((lane >> 4) << 3);
                LDSM4(afh[i], base + row * LDSB + kc * 2);
                if (MODE == 3) {
                    afh[i][0] = prob_tf(afh[i][0], tq2[i][0], ss2[i][0]);
                    afh[i][2] = prob_tf(afh[i][2], tq2[i][0], ss2[i][0]);
                    afh[i][1] = prob_tf(afh[i][1], tq2[i][1], ss2[i][1]);
                    afh[i][3] = prob_tf(afh[i][3], tq2[i][1], ss2[i][1]);
                }
            }
            uint32_t bfh[NJ][2];
            #pragma unroll
            for (int jp = 0; jp < NJ / 2; jp++) {
                const int nrow = wtn + jp * 16 + (lane & 7) + ((lane & 16) ? 8 : 0);
                const int kc   = ks * 16 + ((lane & 8) ? 8 : 0);
                uint32_t t[4];
                LDSM4(t, base + ABYTES + nrow * LDSB + kc * 2);
                bfh[2*jp][0]   = t[0]; bfh[2*jp][1]   = t[1];
                bfh[2*jp+1][0] = t[2]; bfh[2*jp+1][1] = t[3];
            }
            #pragma unroll
            for (int i = 0; i < MI; i++)
                #pragma unroll
                for (int j = 0; j < NJ; j++)
                    MMA16816(acc[i][j], afh[i], bfh[j]);
        }
        __syncthreads();
    }

    // ---- epilogue ----
    #pragma unroll
    for (int i = 0; i < MI; i++)
        #pragma unroll
        for (int j = 0; j < NJ; j++) {
            const int colb = n0 + wtn + j * 8 + (lane & 3) * 2;
            #pragma unroll
            for (int h = 0; h < 2; h++) {
                const int row = m0 + wtm + i * 16 + (lane >> 2) + h * 8;
                float v0 = acc[i][j][2*h], v1 = acc[i][j][2*h+1];
                if (MODE == 3) {
                    *(uint32_t*)(Chi + (long)row * ldc + z * 64 + colb)
                        = pack2(__float2half_rn(v0), __float2half_rn(v1));
                } else if (MODE == 4) {
                    const long idx = (long)row * ldc + colb;
                    const float2 b2 = *(const float2*)(bias + colb);
                    const float2 r2 = *(const float2*)(resid + idx);
                    *(float2*)(Cf + idx) = make_float2(v0 + b2.x + r2.x,
                                                       v1 + b2.y + r2.y);
                } else if (MODE == 5) {
                    const float2 b2 = *(const float2*)(bias + colb);
                    v0 = fmaxf(v0 + b2.x, 0.f); v1 = fmaxf(v1 + b2.y, 0.f);
                    *(uint32_t*)(Chi + (long)row * ldc + colb)
                        = pack2(__float2half_rn(v0), __float2half_rn(v1));
                } else {  // MODE 7
                    const float* bpt = (z == 0) ? bias : (z == 1 ? bias2 : bias3);
                    const float2 b2 = *(const float2*)(bpt + colb);
                    v0 += b2.x; v1 += b2.y;
                    if (z == 0) {
                        *(uint32_t*)(Chi + (long)row * ldc + colb)
                            = pack2(__float2half_rn(v0), __float2half_rn(v1));
                    } else if (z == 1) {
                        *(uint32_t*)(Chi2 + (long)row * ldc + colb)
                            = pack2(__float2half_rn(v0), __float2half_rn(v1));
                    } else {
                        const int rk = rankp[row];
                        if (rk >= 0) {
                            Chi3[(long)colb * S_ + rk]       = __float2half_rn(v0);
                            Chi3[(long)(colb + 1) * S_ + rk] = __float2half_rn(v1);
                        }
                    }
                }
            }
        }
}

template<typename T>
static T* sym(const void* s) {
    void* p = nullptr;
    cudaGetSymbolAddress(&p, s);
    return (T*)p;
}

extern "C" void kernel_launch(void* const* d_in, const int* in_sizes, int n_in,
                              void* d_out, int out_size)
{
    const float* inputs = (const float*)d_in[0];
    const int*   mask   = (const int*)  d_in[1];
    const float* wq = (const float*)d_in[2];  const float* bq = (const float*)d_in[3];
    const float* wk = (const float*)d_in[4];  const float* bk = (const float*)d_in[5];
    const float* wv = (const float*)d_in[6];  const float* bv = (const float*)d_in[7];
    const float* wo = (const float*)d_in[8];  const float* bo = (const float*)d_in[9];
    const float* ln1_a = (const float*)d_in[10]; const float* ln1_b = (const float*)d_in[11];
    const float* w1 = (const float*)d_in[12]; const float* b1 = (const float*)d_in[13];
    const float* w2 = (const float*)d_in[14]; const float* b2 = (const float*)d_in[15];
    const float* ln2_a = (const float*)d_in[16]; const float* ln2_b = (const float*)d_in[17];
    float* out = (float*)d_out;

    __half *sx  = sym<__half>(g_sx);
    float2 *tau = sym<float2>(g_tau);
    __half *x   = sym<__half>(g_x);
    __half *q   = sym<__half>(g_q);
    __half *k   = sym<__half>(g_k);
    __half *vt  = sym<__half>(g_vt);
    __half *at  = sym<__half>(g_at);
    float  *y   = sym<float>(g_y);
    __half *h1  = sym<__half>(g_h1);
    __half *wqkv = sym<__half>(g_wqkv);
    __half *woh = sym<__half>(g_wo);
    __half *w1h = sym<__half>(g_w1), *w2h = sym<__half>(g_w2);
    int *idx  = sym<int>(g_idx);
    int *rank = sym<int>(g_rank);
    int *meta = sym<int>(g_meta);

    constexpr int SM_GP = 2 * (128 + 64) * 144;   // 55296
    constexpr int SM_SC = 3 * 128 * 144;          // 55296

    cudaFuncSetAttribute((const void*)gemm_mma<128,64,32,32,7,3>,
                         cudaFuncAttributeMaxDynamicSharedMemorySize, SM_GP);
    cudaFuncSetAttribute((const void*)gemm_mma<128,64,32,32,4,3>,
                         cudaFuncAttributeMaxDynamicSharedMemorySize, SM_GP);
    cudaFuncSetAttribute((const void*)gemm_mma<128,64,32,32,5,3>,
                         cudaFuncAttributeMaxDynamicSharedMemorySize, SM_GP);
    cudaFuncSetAttribute((const void*)gemm_mma<128,64,32,32,3,3>,
                         cudaFuncAttributeMaxDynamicSharedMemorySize, SM_GP);
    cudaFuncSetAttribute((const void*)scores_mma,
                         cudaFuncAttributeMaxDynamicSharedMemorySize, SM_SC);

    const dim3 blk256(256);

    // weights -> fp16 + mask scan + LN1, one launch
    cvt_w<<<12545, blk256>>>((const float4*)wq, (const float4*)wk, (const float4*)wv,
                             (const float4*)wo, (const float4*)w1, (const float4*)w2,
                             (uint2*)wqkv, (uint2*)woh, (uint2*)w1h, (uint2*)w2h,
                             mask, rank, idx, meta,
                             inputs, ln1_a, ln1_b, x);

    // fused QKV: V epilogue writes compacted transposed V
    gemm_mma<128,64,32,32,7,3><<<dim3(D_/64, S_/128, 3), blk256, SM_GP>>>(
        x, D_, 0, wqkv, D_, (long)D_ * D_, D_, nullptr, rank,
        nullptr, 0, D_, q, k, vt,
        bq, bk, bv, nullptr, 0.f);

    // scores over compacted keys; alpha = 0.125 * 0.5 = 0.0625
    scores_mma<<<dim3(4, S_/128, H_), blk256, SM_SC>>>(q, k, idx, meta, sx, 0.0625f);

    // entmax stats: half2 Newton + fp32 refinement, width-matched dispatch
    entmax_stats<<<H_ * S_ / 8, blk256>>>(sx, meta, tau);

    // PV: half2 in-register probs, K = cnt_pad from meta
    gemm_mma<128,64,32,32,3,3><<<dim3(1, S_/128, H_), blk256, SM_GP>>>(
        sx, S_, (long)S_ * S_, vt, S_, (long)64 * S_, 0, meta, nullptr,
        nullptr, 0, D_, at, nullptr, nullptr,
        (const float*)tau, nullptr, nullptr, nullptr, 0.f);

    // Wo + residual -> y (fp32)
    gemm_mma<128,64,32,32,4,3><<<dim3(D_/64, S_/128), blk256, SM_GP>>>(
        at, D_, 0, woh, D_, 0, D_, nullptr, nullptr,
        y, 0, D_, nullptr, nullptr, nullptr,
        bo, nullptr, nullptr, inputs, 0.f);

    ln_kernel<<<S_ / 8, blk256>>>(y, ln2_a, ln2_b, x);

    // FFN1: relu(x @ w1^T + b1) -> fp16
    gemm_mma<128,64,32,32,5,3><<<dim3(DFF_/64, S_/128), blk256, SM_GP>>>(
        x, D_, 0, w1h, D_, 0, D_, nullptr, nullptr,
        nullptr, 0, DFF_, h1, nullptr, nullptr,
        b1, nullptr, nullptr, nullptr, 0.f);

    // FFN2 + residual -> out
    gemm_mma<128,64,32,32,4,3><<<dim3(D_/64, S_/128), blk256, SM_GP>>>(
        h1, DFF_, 0, w2h, DFF_, 0, DFF_, nullptr, nullptr,
        out, 0, D_, nullptr, nullptr, nullptr,
        b2, nullptr, nullptr, y, 0.f);
}